// round 5
// baseline (speedup 1.0000x reference)
#include <cuda_runtime.h>
#include <math.h>

#define Bn 4
#define Tn 1024
#define Sn 64
#define En 128
#define NHn 4
#define DHn 32
#define FFn 256
#define Ln 3
#define Cn 4
#define SX 132            // row-major stride (floats)
#define STR 66            // transposed (k-major) stride — even => 8B-aligned row pairs
#define NTHREADS 512

typedef unsigned long long ull;

// ---- packed f32x2 helpers (sm_103a) ----
__device__ __forceinline__ ull pk2(float lo, float hi){
    ull r; asm("mov.b64 %0, {%1,%2};" : "=l"(r) : "f"(lo), "f"(hi)); return r;
}
__device__ __forceinline__ void upk2(ull p, float& lo, float& hi){
    asm("mov.b64 {%0,%1}, %2;" : "=f"(lo), "=f"(hi) : "l"(p));
}
__device__ __forceinline__ ull fma2(ull a, ull b, ull c){
    ull d; asm("fma.rn.f32x2 %0, %1, %2, %3;" : "=l"(d) : "l"(a), "l"(b), "l"(c)); return d;
}
__device__ __forceinline__ ull add2(ull a, ull b){
    ull d; asm("add.rn.f32x2 %0, %1, %2;" : "=l"(d) : "l"(a), "l"(b)); return d;
}

__device__ __forceinline__ float gelu_tanh(float x){
    float x3 = x*x*x;
    float t = tanhf(0.7978845608028654f*(x + 0.044715f*x3));
    return 0.5f*x*(1.0f + t);
}

// ---- layernorm: 8 threads/row; src row-major X, dst TRANSPOSED HT[c][row] ----
// All 8 lanes of a group share `row`, so the guarded group-masked shuffles are safe.
__device__ __forceinline__ void layernorm_t(const float* __restrict__ src,
        float* __restrict__ dstT, const float* __restrict__ g,
        const float* __restrict__ b, int valid)
{
    const int t   = threadIdx.x;
    const int row = t >> 3;           // 512/8 = 64 rows
    const int e   = t & 7;
    if (row < valid){
        const unsigned gmask = 0xFFu << ((t & 31) & ~7);
        const float* xr = src + row*SX;
        float s = 0.f, s2 = 0.f;
        #pragma unroll
        for (int i = 0; i < 16; i++){
            float v = xr[e + 8*i];
            s += v; s2 = fmaf(v, v, s2);
        }
        s  += __shfl_xor_sync(gmask, s, 1);  s2 += __shfl_xor_sync(gmask, s2, 1);
        s  += __shfl_xor_sync(gmask, s, 2);  s2 += __shfl_xor_sync(gmask, s2, 2);
        s  += __shfl_xor_sync(gmask, s, 4);  s2 += __shfl_xor_sync(gmask, s2, 4);
        const float m    = s * 0.0078125f;
        const float rstd = rsqrtf(s2*0.0078125f - m*m + 1e-5f);
        #pragma unroll
        for (int i = 0; i < 16; i++){
            int c = e + 8*i;
            dstT[c*STR + row] = (xr[c] - m)*rstd*g[c] + b[c];
        }
    }
}

// ---- GEMM: dst[r][c] = sum_k srcT[k][r] * W[k][c] + bias[c]
// Work unit = 4 rows x 64 cols, round-robin over 16 warps.
// Lane -> 2 cols; rows -> 2 f32x2 pairs. MODE 0=store 1=add 2=gelu->transposed.
template<int IC, int OC, int MODE>
__device__ __forceinline__ void gemm_t(const float* __restrict__ srcT,
                                       const float* __restrict__ W,
                                       const float* __restrict__ bias,
                                       float* __restrict__ dst, int nrb4)
{
    const int warp = threadIdx.x >> 5;
    const int lane = threadIdx.x & 31;
    const int NCH  = OC / 64;
    const int nunits = nrb4 * NCH;
    for (int u = warp; u < nunits; u += 16){
        const int rb = u / NCH;
        const int ch = u - rb*NCH;
        const int r0 = rb << 2;
        const int c0 = ch*64 + lane*2;
        const float* Wp = W + c0;

        ull acc[2][2];
        {
            const float2 bb = *(const float2*)(bias + c0);
            acc[0][0] = acc[1][0] = pk2(bb.x, bb.x);
            acc[0][1] = acc[1][1] = pk2(bb.y, bb.y);
        }
        float2 wr[4];
        #pragma unroll
        for (int j = 0; j < 4; j++) wr[j] = __ldg((const float2*)(Wp + j*OC));

        #pragma unroll 1
        for (int kk = 0; kk < IC; kk += 4){
            const int kn = (kk + 4 < IC) ? (kk + 4) : kk;   // prefetch next k-group
            float2 wn[4];
            #pragma unroll
            for (int j = 0; j < 4; j++) wn[j] = __ldg((const float2*)(Wp + (kn + j)*OC));
            #pragma unroll
            for (int j = 0; j < 4; j++){
                const ull* hp = (const ull*)(srcT + (kk + j)*STR + r0); // 2 row pairs
                const ull w0 = pk2(wr[j].x, wr[j].x);
                const ull w1 = pk2(wr[j].y, wr[j].y);
                #pragma unroll
                for (int p = 0; p < 2; p++){
                    const ull h = hp[p];
                    acc[p][0] = fma2(h, w0, acc[p][0]);
                    acc[p][1] = fma2(h, w1, acc[p][1]);
                }
            }
            #pragma unroll
            for (int j = 0; j < 4; j++) wr[j] = wn[j];
        }
        #pragma unroll
        for (int p = 0; p < 2; p++){
            float a0, a1, c1r0, c1r1;
            upk2(acc[p][0], a0, a1);      // col c0:   rows r, r+1
            upk2(acc[p][1], c1r0, c1r1);  // col c0+1: rows r, r+1
            const int r = r0 + 2*p;
            if (MODE == 0){
                *(float2*)(dst + r*SX + c0)     = make_float2(a0, c1r0);
                *(float2*)(dst + (r+1)*SX + c0) = make_float2(a1, c1r1);
            } else if (MODE == 1){
                float2* d0 = (float2*)(dst + r*SX + c0);
                float2* d1 = (float2*)(dst + (r+1)*SX + c0);
                float2 x0 = *d0, x1 = *d1;
                x0.x += a0; x0.y += c1r0; *d0 = x0;
                x1.x += a1; x1.y += c1r1; *d1 = x1;
            } else {
                dst[c0*STR + r]       = gelu_tanh(a0);
                dst[c0*STR + r + 1]   = gelu_tanh(a1);
                dst[(c0+1)*STR + r]   = gelu_tanh(c1r0);
                dst[(c0+1)*STR + r+1] = gelu_tanh(c1r1);
            }
        }
    }
}

// ---- attention: 2 threads per (head,row), each owns 32 keys; merged via
// PAIR-SCOPED shuffles (mask = the 2 participating lanes only — both lanes of
// a pair share `row`, so they are active/inactive together; full-warp masks
// inside the guard deadlock when some rows are dead).
__device__ __forceinline__ void attention_t(const float* __restrict__ Qb,
        const float* __restrict__ Kb, const float* __restrict__ Vb,
        float* __restrict__ HTo, int valid)
{
    const int t    = threadIdx.x;
    const int lane = t & 31;
    const int half = t & 1;
    const int u    = t >> 1;          // 256 units
    const int head = u >> 6;
    const int row  = u & 63;
    const int base = head * DHn;
    const float scale = 0.17677669529663687f; // 1/sqrt(32)
    const unsigned pmask = 0x3u << (lane & 30);   // this lane + its partner

    if (row < valid){
        ull qp[16];
        const ull* qpt = (const ull*)(Qb + row*SX + base);
        #pragma unroll
        for (int j = 0; j < 16; j++) qp[j] = qpt[j];

        const int tt0 = half << 5;    // this thread's 32 keys
        float s[32];
        float m = -1e30f;
        #pragma unroll
        for (int i = 0; i < 32; ++i){
            const int tt = tt0 + i;
            if (tt < valid){
                const ull* kpt = (const ull*)(Kb + tt*SX + base);
                ull acc2 = pk2(0.f, 0.f);
                #pragma unroll
                for (int j = 0; j < 16; j++) acc2 = fma2(qp[j], kpt[j], acc2);
                float lo, hi; upk2(acc2, lo, hi);
                s[i] = (lo + hi) * scale;
                m = fmaxf(m, s[i]);
            } else s[i] = -1e30f;
        }
        m = fmaxf(m, __shfl_xor_sync(pmask, m, 1));   // global max (pair)
        float sum = 0.f;
        #pragma unroll
        for (int i = 0; i < 32; ++i){
            const int tt = tt0 + i;
            float e = (tt < valid) ? __expf(s[i] - m) : 0.f;
            s[i] = e; sum += e;
        }
        sum += __shfl_xor_sync(pmask, sum, 1);         // global sum (pair)

        ull op[16];
        #pragma unroll
        for (int j = 0; j < 16; j++) op[j] = pk2(0.f, 0.f);
        #pragma unroll
        for (int i = 0; i < 32; ++i){
            const int tt = tt0 + i;
            if (tt < valid){
                const ull ad = pk2(s[i], s[i]);
                const ull* vpt = (const ull*)(Vb + tt*SX + base);
                #pragma unroll
                for (int j = 0; j < 16; j++) op[j] = fma2(ad, vpt[j], op[j]);
            }
        }
        const float inv = 1.0f / sum;
        // merge partner's partials; each half writes 8 ull (16 dims)
        #pragma unroll
        for (int j = 0; j < 16; j++)
            op[j] = add2(op[j], __shfl_xor_sync(pmask, op[j], 1));
        const int j0 = half << 3;
        #pragma unroll
        for (int jj = 0; jj < 8; jj++){
            const int j = j0 + jj;
            float lo, hi; upk2(op[j], lo, hi);
            HTo[(base + 2*j)*STR + row]     = lo * inv;
            HTo[(base + 2*j + 1)*STR + row] = hi * inv;
        }
    }
}

#define SMEM_FLOATS (Sn*SX /*X*/ + En*STR /*HT*/ + 3*Sn*SX /*QKV*/ + 2*Sn*16 /*rope*/)
#define SMEM_BYTES  (SMEM_FLOATS*4)

__global__ void __launch_bounds__(NTHREADS, 1) rowinteraction_kernel(
    const float* __restrict__ emb,  const float* __restrict__ cls,
    const float* __restrict__ ln1g, const float* __restrict__ ln1b,
    const float* __restrict__ wq,   const float* __restrict__ bq,
    const float* __restrict__ wk,   const float* __restrict__ bk,
    const float* __restrict__ wv,   const float* __restrict__ bv,
    const float* __restrict__ wo,   const float* __restrict__ bo,
    const float* __restrict__ ln2g, const float* __restrict__ ln2b,
    const float* __restrict__ w1,   const float* __restrict__ b1,
    const float* __restrict__ w2,   const float* __restrict__ b2,
    const float* __restrict__ og,   const float* __restrict__ ob,
    const int*   __restrict__ dvec, float* __restrict__ out)
{
    extern __shared__ float smf[];
    float* X   = smf;                 // [64][132] residual (row-major)
    float* HT  = X  + Sn*SX;          // [128][66] transposed activations
    float* Qb  = HT + En*STR;         // [64][132]
    float* Kb  = Qb + Sn*SX;
    float* Vb  = Kb + Sn*SX;
    float* FFT = Qb;                  // [256][66] overlays Q+K
    float* RC  = Vb + Sn*SX;          // rope cos [64][16]
    float* RS  = RC + Sn*16;

    const int tid   = threadIdx.x;
    const int n     = blockIdx.x;
    const int bidx  = n >> 10;        // T = 1024
    const int valid = dvec[bidx] + Cn;          // 4..63
    const int nrb4  = (valid + 3) >> 2;         // live 4-row blocks, 1..16

    for (int idx = tid; idx < Sn*16; idx += NTHREADS){
        int pos = idx >> 4, f = idx & 15;
        float inv = expf(-((float)(2*f) / (float)DHn) * logf(100000.0f));
        float ang = (float)pos * inv;
        RC[idx] = cosf(ang); RS[idx] = sinf(ang);
    }
    for (int idx = tid; idx < Sn*En; idx += NTHREADS){
        int r = idx >> 7, c = idx & 127;
        float v = (r < Cn) ? cls[r*En + c] : emb[((size_t)n*Sn + r)*En + c];
        X[r*SX + c] = v;
    }
    __syncthreads();

    for (int l = 0; l < Ln; ++l){
        layernorm_t(X, HT, ln1g + l*En, ln1b + l*En, valid);
        __syncthreads();
        gemm_t<En, En, 0>(HT, wq + l*En*En, bq + l*En, Qb, nrb4);
        gemm_t<En, En, 0>(HT, wk + l*En*En, bk + l*En, Kb, nrb4);
        gemm_t<En, En, 0>(HT, wv + l*En*En, bv + l*En, Vb, nrb4);
        __syncthreads();
        for (int idx = tid; idx < Sn*NHn*16; idx += NTHREADS){
            int row = idx >> 6;
            if (row < valid){
                int hj = idx & 63; int h = hj >> 4; int j = hj & 15;
                float cc = RC[row*16 + j], ss = RS[row*16 + j];
                int o1 = row*SX + h*DHn + j, o2 = o1 + 16;
                float q1 = Qb[o1], q2 = Qb[o2];
                Qb[o1] = q1*cc - q2*ss;  Qb[o2] = q2*cc + q1*ss;
                float k1 = Kb[o1], k2 = Kb[o2];
                Kb[o1] = k1*cc - k2*ss;  Kb[o2] = k2*cc + k1*ss;
            }
        }
        __syncthreads();
        attention_t(Qb, Kb, Vb, HT, valid);
        __syncthreads();
        gemm_t<En, En, 1>(HT, wo + l*En*En, bo + l*En, X, nrb4);     // x += o@wo+bo
        __syncthreads();
        layernorm_t(X, HT, ln2g + l*En, ln2b + l*En, valid);
        __syncthreads();
        gemm_t<En, FFn, 2>(HT, w1 + l*En*FFn, b1 + l*FFn, FFT, nrb4); // gelu -> FFT
        __syncthreads();
        gemm_t<FFn, En, 1>(FFT, w2 + l*FFn*En, b2 + l*En, X, nrb4);   // x += ff@w2+b2
        __syncthreads();
    }

    // Epilogue: out-layernorm rows 0..3, write (B,T,C*E). Whole warps 0..3
    // participate uniformly -> full-warp shuffles are safe here.
    const int warp = tid >> 5, lane = tid & 31;
    if (warp < Cn){
        const float4 xv = *(const float4*)(X + warp*SX + lane*4);
        float s  = xv.x + xv.y + xv.z + xv.w;
        float s2 = xv.x*xv.x + xv.y*xv.y + xv.z*xv.z + xv.w*xv.w;
        #pragma unroll
        for (int o = 16; o; o >>= 1){
            s  += __shfl_xor_sync(0xffffffffu, s,  o);
            s2 += __shfl_xor_sync(0xffffffffu, s2, o);
        }
        const float m    = s * 0.0078125f;
        const float rstd = rsqrtf(s2*0.0078125f - m*m + 1e-5f);
        const float4 gv  = *(const float4*)(og + lane*4);
        const float4 bv4 = *(const float4*)(ob + lane*4);
        float4 ovv;
        ovv.x = (xv.x - m)*rstd*gv.x + bv4.x;
        ovv.y = (xv.y - m)*rstd*gv.y + bv4.y;
        ovv.z = (xv.z - m)*rstd*gv.z + bv4.z;
        ovv.w = (xv.w - m)*rstd*gv.w + bv4.w;
        *(float4*)(out + (size_t)n*(Cn*En) + warp*En + lane*4) = ovv;
    }
}

extern "C" void kernel_launch(void* const* d_in, const int* in_sizes, int n_in,
                              void* d_out, int out_size)
{
    (void)in_sizes; (void)n_in; (void)out_size;
    cudaFuncSetAttribute(rowinteraction_kernel,
                         cudaFuncAttributeMaxDynamicSharedMemorySize, SMEM_BYTES);
    rowinteraction_kernel<<<Bn*Tn, NTHREADS, SMEM_BYTES>>>(
        (const float*)d_in[0],  (const float*)d_in[1],
        (const float*)d_in[2],  (const float*)d_in[3],
        (const float*)d_in[4],  (const float*)d_in[5],
        (const float*)d_in[6],  (const float*)d_in[7],
        (const float*)d_in[8],  (const float*)d_in[9],
        (const float*)d_in[10], (const float*)d_in[11],
        (const float*)d_in[12], (const float*)d_in[13],
        (const float*)d_in[14], (const float*)d_in[15],
        (const float*)d_in[16], (const float*)d_in[17],
        (const float*)d_in[18], (const float*)d_in[19],
        (const int*)d_in[20],   (float*)d_out);
}

// round 7
// speedup vs baseline: 1.3268x; 1.3268x over previous
#include <cuda_runtime.h>
#include <math.h>

#define Bn 4
#define Tn 1024
#define Sn 64
#define En 128
#define NHn 4
#define DHn 32
#define FFn 256
#define Ln 3
#define Cn 4
#define SX 132            // row-major stride (floats)
#define STR 66            // transposed (k-major) stride
#define NTHREADS 512

typedef unsigned long long ull;

// ---- packed f32x2 helpers (sm_103a) ----
__device__ __forceinline__ ull pk2(float lo, float hi){
    ull r; asm("mov.b64 %0, {%1,%2};" : "=l"(r) : "f"(lo), "f"(hi)); return r;
}
__device__ __forceinline__ void upk2(ull p, float& lo, float& hi){
    asm("mov.b64 {%0,%1}, %2;" : "=f"(lo), "=f"(hi) : "l"(p));
}
__device__ __forceinline__ ull fma2(ull a, ull b, ull c){
    ull d; asm("fma.rn.f32x2 %0, %1, %2, %3;" : "=l"(d) : "l"(a), "l"(b), "l"(c)); return d;
}
__device__ __forceinline__ ull add2(ull a, ull b){
    ull d; asm("add.rn.f32x2 %0, %1, %2;" : "=l"(d) : "l"(a), "l"(b)); return d;
}

__device__ __forceinline__ float gelu_tanh(float x){
    float x3 = x*x*x;
    float t = tanhf(0.7978845608028654f*(x + 0.044715f*x3));
    return 0.5f*x*(1.0f + t);
}

// ---- layernorm: 8 threads/row; src row-major X, dst TRANSPOSED HT[c][row] ----
__device__ __forceinline__ void layernorm_t(const float* __restrict__ src,
        float* __restrict__ dstT, const float* __restrict__ g,
        const float* __restrict__ b, int valid)
{
    const int t   = threadIdx.x;
    const int row = t >> 3;           // 64 rows
    const int e   = t & 7;
    if (row < valid){
        const unsigned gmask = 0xFFu << ((t & 31) & ~7);
        const float* xr = src + row*SX;
        float s = 0.f, s2 = 0.f;
        #pragma unroll
        for (int i = 0; i < 16; i++){
            float v = xr[e + 8*i];
            s += v; s2 = fmaf(v, v, s2);
        }
        s  += __shfl_xor_sync(gmask, s, 1);  s2 += __shfl_xor_sync(gmask, s2, 1);
        s  += __shfl_xor_sync(gmask, s, 2);  s2 += __shfl_xor_sync(gmask, s2, 2);
        s  += __shfl_xor_sync(gmask, s, 4);  s2 += __shfl_xor_sync(gmask, s2, 4);
        const float m    = s * 0.0078125f;
        const float rstd = rsqrtf(s2*0.0078125f - m*m + 1e-5f);
        #pragma unroll
        for (int i = 0; i < 16; i++){
            int c = e + 8*i;
            dstT[c*STR + row] = (xr[c] - m)*rstd*g[c] + b[c];
        }
    }
}

// ---- GEMM work unit: 8 rows x 64 cols; lane -> 2 cols, rows -> 4 f32x2 pairs.
// MODE 0 = store row-major; 1 = add into row-major; 2 = gelu -> transposed.
template<int IC, int OC, int MODE>
__device__ __forceinline__ void gemm_unit(const float* __restrict__ srcT,
        const float* __restrict__ W, const float* __restrict__ bias,
        float* __restrict__ dst, int r0, int c0)
{
    const float* Wp = W + c0;
    ull acc[4][2];
    {
        const float2 bb = *(const float2*)(bias + c0);
        const ull b0 = pk2(bb.x, bb.x), b1 = pk2(bb.y, bb.y);
        #pragma unroll
        for (int p = 0; p < 4; p++){ acc[p][0] = b0; acc[p][1] = b1; }
    }
    float2 wr[4];
    #pragma unroll
    for (int j = 0; j < 4; j++) wr[j] = __ldg((const float2*)(Wp + j*OC));

    #pragma unroll 1
    for (int kk = 0; kk < IC; kk += 4){
        const int kn = (kk + 4 < IC) ? (kk + 4) : kk;   // prefetch next k-group
        float2 wn[4];
        #pragma unroll
        for (int j = 0; j < 4; j++) wn[j] = __ldg((const float2*)(Wp + (kn + j)*OC));
        #pragma unroll
        for (int j = 0; j < 4; j++){
            const ull* hp = (const ull*)(srcT + (kk + j)*STR + r0); // 4 row pairs
            const ull w0 = pk2(wr[j].x, wr[j].x);
            const ull w1 = pk2(wr[j].y, wr[j].y);
            #pragma unroll
            for (int p = 0; p < 4; p++){
                const ull h = hp[p];
                acc[p][0] = fma2(h, w0, acc[p][0]);
                acc[p][1] = fma2(h, w1, acc[p][1]);
            }
        }
        #pragma unroll
        for (int j = 0; j < 4; j++) wr[j] = wn[j];
    }
    #pragma unroll
    for (int p = 0; p < 4; p++){
        float a0, a1, c1r0, c1r1;
        upk2(acc[p][0], a0, a1);      // col c0:   rows r, r+1
        upk2(acc[p][1], c1r0, c1r1);  // col c0+1: rows r, r+1
        const int r = r0 + 2*p;
        if (MODE == 0){
            *(float2*)(dst + r*SX + c0)     = make_float2(a0, c1r0);
            *(float2*)(dst + (r+1)*SX + c0) = make_float2(a1, c1r1);
        } else if (MODE == 1){
            float2* d0 = (float2*)(dst + r*SX + c0);
            float2* d1 = (float2*)(dst + (r+1)*SX + c0);
            float2 x0 = *d0, x1 = *d1;
            x0.x += a0; x0.y += c1r0; *d0 = x0;
            x1.x += a1; x1.y += c1r1; *d1 = x1;
        } else {
            dst[c0*STR + r]       = gelu_tanh(a0);
            dst[c0*STR + r + 1]   = gelu_tanh(a1);
            dst[(c0+1)*STR + r]   = gelu_tanh(c1r0);
            dst[(c0+1)*STR + r+1] = gelu_tanh(c1r1);
        }
    }
}

// single-GEMM dispatcher: units = nrb8 * (OC/64), round-robin over 16 warps
template<int IC, int OC, int MODE>
__device__ __forceinline__ void gemm_t(const float* __restrict__ srcT,
        const float* __restrict__ W, const float* __restrict__ bias,
        float* __restrict__ dst, int nrb8)
{
    const int warp = threadIdx.x >> 5;
    const int lane = threadIdx.x & 31;
    const int NCH  = OC / 64;
    const int nunits = nrb8 * NCH;
    for (int u = warp; u < nunits; u += 16){
        const int rb = u / NCH;
        const int ch = u - rb*NCH;
        gemm_unit<IC, OC, MODE>(srcT, W, bias, dst, rb << 3, ch*64 + lane*2);
    }
}

// fused Q/K/V dispatcher: 3*nrb8*2 units over 16 warps (no inter-GEMM sync/tail)
__device__ __forceinline__ void gemm_qkv(const float* __restrict__ srcT,
        const float* __restrict__ wq, const float* __restrict__ bq,
        const float* __restrict__ wk, const float* __restrict__ bk,
        const float* __restrict__ wv, const float* __restrict__ bv,
        float* __restrict__ Qb, float* __restrict__ Kb, float* __restrict__ Vb,
        int nrb8)
{
    const int warp = threadIdx.x >> 5;
    const int lane = threadIdx.x & 31;
    const int NU   = nrb8 * 2;       // units per gemm
    for (int u = warp; u < 3*NU; u += 16){
        int g = u / NU;
        int rem = u - g*NU;
        int rb = rem >> 1, ch = rem & 1;
        const float *W, *bi; float *dst;
        if      (g == 0){ W = wq; bi = bq; dst = Qb; }
        else if (g == 1){ W = wk; bi = bk; dst = Kb; }
        else            { W = wv; bi = bv; dst = Vb; }
        gemm_unit<En, En, 0>(srcT, W, bi, dst, rb << 3, ch*64 + lane*2);
    }
}

// ---- attention: 2 threads per (head,row); PAIR-SCOPED shuffles (safe under guard)
__device__ __forceinline__ void attention_t(const float* __restrict__ Qb,
        const float* __restrict__ Kb, const float* __restrict__ Vb,
        float* __restrict__ HTo, int valid)
{
    const int t    = threadIdx.x;
    const int lane = t & 31;
    const int half = t & 1;
    const int u    = t >> 1;          // 256 units
    const int head = u >> 6;
    const int row  = u & 63;
    const int base = head * DHn;
    const float scale = 0.17677669529663687f; // 1/sqrt(32)
    const unsigned pmask = 0x3u << (lane & 30);

    if (row < valid){
        ull qp[16];
        const ull* qpt = (const ull*)(Qb + row*SX + base);
        #pragma unroll
        for (int j = 0; j < 16; j++) qp[j] = qpt[j];

        const int tt0 = half << 5;
        float s[32];
        float m = -1e30f;
        #pragma unroll
        for (int i = 0; i < 32; ++i){
            const int tt = tt0 + i;
            if (tt < valid){
                const ull* kpt = (const ull*)(Kb + tt*SX + base);
                ull acc2 = pk2(0.f, 0.f);
                #pragma unroll
                for (int j = 0; j < 16; j++) acc2 = fma2(qp[j], kpt[j], acc2);
                float lo, hi; upk2(acc2, lo, hi);
                s[i] = (lo + hi) * scale;
                m = fmaxf(m, s[i]);
            } else s[i] = -1e30f;
        }
        m = fmaxf(m, __shfl_xor_sync(pmask, m, 1));
        float sum = 0.f;
        #pragma unroll
        for (int i = 0; i < 32; ++i){
            const int tt = tt0 + i;
            float e = (tt < valid) ? __expf(s[i] - m) : 0.f;
            s[i] = e; sum += e;
        }
        sum += __shfl_xor_sync(pmask, sum, 1);

        ull op[16];
        #pragma unroll
        for (int j = 0; j < 16; j++) op[j] = pk2(0.f, 0.f);
        #pragma unroll
        for (int i = 0; i < 32; ++i){
            const int tt = tt0 + i;
            if (tt < valid){
                const ull ad = pk2(s[i], s[i]);
                const ull* vpt = (const ull*)(Vb + tt*SX + base);
                #pragma unroll
                for (int j = 0; j < 16; j++) op[j] = fma2(ad, vpt[j], op[j]);
            }
        }
        const float inv = 1.0f / sum;
        #pragma unroll
        for (int j = 0; j < 16; j++)
            op[j] = add2(op[j], __shfl_xor_sync(pmask, op[j], 1));
        const int j0 = half << 3;
        #pragma unroll
        for (int jj = 0; jj < 8; jj++){
            const int j = j0 + jj;
            float lo, hi; upk2(op[j], lo, hi);
            HTo[(base + 2*j)*STR + row]     = lo * inv;
            HTo[(base + 2*j + 1)*STR + row] = hi * inv;
        }
    }
}

#define SMEM_FLOATS (Sn*SX /*X*/ + En*STR /*HT*/ + 3*Sn*SX /*QKV*/ + 2*Sn*16 /*rope*/)
#define SMEM_BYTES  (SMEM_FLOATS*4)

__global__ void __launch_bounds__(NTHREADS, 1) rowinteraction_kernel(
    const float* __restrict__ emb,  const float* __restrict__ cls,
    const float* __restrict__ ln1g, const float* __restrict__ ln1b,
    const float* __restrict__ wq,   const float* __restrict__ bq,
    const float* __restrict__ wk,   const float* __restrict__ bk,
    const float* __restrict__ wv,   const float* __restrict__ bv,
    const float* __restrict__ wo,   const float* __restrict__ bo,
    const float* __restrict__ ln2g, const float* __restrict__ ln2b,
    const float* __restrict__ w1,   const float* __restrict__ b1,
    const float* __restrict__ w2,   const float* __restrict__ b2,
    const float* __restrict__ og,   const float* __restrict__ ob,
    const int*   __restrict__ dvec, float* __restrict__ out)
{
    extern __shared__ float smf[];
    float* X   = smf;                 // [64][132] residual (row-major)
    float* HT  = X  + Sn*SX;          // [128][66] transposed activations
    float* Qb  = HT + En*STR;         // [64][132]
    float* Kb  = Qb + Sn*SX;
    float* Vb  = Kb + Sn*SX;
    float* FFT = Qb;                  // [256][66] overlays Q+K
    float* RC  = Vb + Sn*SX;          // rope cos [64][16]
    float* RS  = RC + Sn*16;

    const int tid   = threadIdx.x;
    const int n     = blockIdx.x;
    const int bidx  = n >> 10;        // T = 1024
    const int valid = dvec[bidx] + Cn;          // 4..63
    const int nrb8  = (valid + 7) >> 3;         // live 8-row blocks, 1..8

    for (int idx = tid; idx < Sn*16; idx += NTHREADS){
        int pos = idx >> 4, f = idx & 15;
        float inv = expf(-((float)(2*f) / (float)DHn) * logf(100000.0f));
        float ang = (float)pos * inv;
        RC[idx] = cosf(ang); RS[idx] = sinf(ang);
    }
    for (int idx = tid; idx < Sn*En; idx += NTHREADS){
        int r = idx >> 7, c = idx & 127;
        float v = (r < Cn) ? cls[r*En + c] : emb[((size_t)n*Sn + r)*En + c];
        X[r*SX + c] = v;
    }
    __syncthreads();

    for (int l = 0; l < Ln; ++l){
        layernorm_t(X, HT, ln1g + l*En, ln1b + l*En, valid);
        __syncthreads();
        gemm_qkv(HT, wq + l*En*En, bq + l*En, wk + l*En*En, bk + l*En,
                 wv + l*En*En, bv + l*En, Qb, Kb, Vb, nrb8);
        __syncthreads();
        for (int idx = tid; idx < Sn*NHn*16; idx += NTHREADS){
            int row = idx >> 6;
            if (row < valid){
                int hj = idx & 63; int h = hj >> 4; int j = hj & 15;
                float cc = RC[row*16 + j], ss = RS[row*16 + j];
                int o1 = row*SX + h*DHn + j, o2 = o1 + 16;
                float q1 = Qb[o1], q2 = Qb[o2];
                Qb[o1] = q1*cc - q2*ss;  Qb[o2] = q2*cc + q1*ss;
                float k1 = Kb[o1], k2 = Kb[o2];
                Kb[o1] = k1*cc - k2*ss;  Kb[o2] = k2*cc + k1*ss;
            }
        }
        __syncthreads();
        attention_t(Qb, Kb, Vb, HT, valid);
        __syncthreads();
        gemm_t<En, En, 1>(HT, wo + l*En*En, bo + l*En, X, nrb8);      // x += o@wo+bo
        __syncthreads();
        layernorm_t(X, HT, ln2g + l*En, ln2b + l*En, valid);
        __syncthreads();
        gemm_t<En, FFn, 2>(HT, w1 + l*En*FFn, b1 + l*FFn, FFT, nrb8); // gelu -> FFT
        __syncthreads();
        gemm_t<FFn, En, 1>(FFT, w2 + l*FFn*En, b2 + l*En, X, nrb8);   // x += ff@w2+b2
        __syncthreads();
    }

    // Epilogue: out-layernorm rows 0..3, write (B,T,C*E)
    const int warp = tid >> 5, lane = tid & 31;
    if (warp < Cn){
        const float4 xv = *(const float4*)(X + warp*SX + lane*4);
        float s  = xv.x + xv.y + xv.z + xv.w;
        float s2 = xv.x*xv.x + xv.y*xv.y + xv.z*xv.z + xv.w*xv.w;
        #pragma unroll
        for (int o = 16; o; o >>= 1){
            s  += __shfl_xor_sync(0xffffffffu, s,  o);
            s2 += __shfl_xor_sync(0xffffffffu, s2, o);
        }
        const float m    = s * 0.0078125f;
        const float rstd = rsqrtf(s2*0.0078125f - m*m + 1e-5f);
        const float4 gv  = *(const float4*)(og + lane*4);
        const float4 bv4 = *(const float4*)(ob + lane*4);
        float4 ovv;
        ovv.x = (xv.x - m)*rstd*gv.x + bv4.x;
        ovv.y = (xv.y - m)*rstd*gv.y + bv4.y;
        ovv.z = (xv.z - m)*rstd*gv.z + bv4.z;
        ovv.w = (xv.w - m)*rstd*gv.w + bv4.w;
        *(float4*)(out + (size_t)n*(Cn*En) + warp*En + lane*4) = ovv;
    }
}

extern "C" void kernel_launch(void* const* d_in, const int* in_sizes, int n_in,
                              void* d_out, int out_size)
{
    (void)in_sizes; (void)n_in; (void)out_size;
    cudaFuncSetAttribute(rowinteraction_kernel,
                         cudaFuncAttributeMaxDynamicSharedMemorySize, SMEM_BYTES);
    rowinteraction_kernel<<<Bn*Tn, NTHREADS, SMEM_BYTES>>>(
        (const float*)d_in[0],  (const float*)d_in[1],
        (const float*)d_in[2],  (const float*)d_in[3],
        (const float*)d_in[4],  (const float*)d_in[5],
        (const float*)d_in[6],  (const float*)d_in[7],
        (const float*)d_in[8],  (const float*)d_in[9],
        (const float*)d_in[10], (const float*)d_in[11],
        (const float*)d_in[12], (const float*)d_in[13],
        (const float*)d_in[14], (const float*)d_in[15],
        (const float*)d_in[16], (const float*)d_in[17],
        (const float*)d_in[18], (const float*)d_in[19],
        (const int*)d_in[20],   (float*)d_out);
}

// round 8
// speedup vs baseline: 1.6673x; 1.2566x over previous
#include <cuda_runtime.h>
#include <math.h>
#include <stdint.h>

#define Bn 4
#define Tn 1024
#define Sn 64
#define En 128
#define NHn 4
#define DHn 32
#define FFn 256
#define Ln 3
#define Cn 4
#define SX 132            // row-major stride (floats); 132 mod 32 = 4 -> conflict-free frags
#define SF 260            // FF row-major stride; 260 mod 32 = 4
#define NTHREADS 512

typedef unsigned long long ull;

// ---- packed f32x2 helpers (sm_103a) ----
__device__ __forceinline__ ull pk2(float lo, float hi){
    ull r; asm("mov.b64 %0, {%1,%2};" : "=l"(r) : "f"(lo), "f"(hi)); return r;
}
__device__ __forceinline__ void upk2(ull p, float& lo, float& hi){
    asm("mov.b64 {%0,%1}, %2;" : "=f"(lo), "=f"(hi) : "l"(p));
}
__device__ __forceinline__ ull fma2(ull a, ull b, ull c){
    ull d; asm("fma.rn.f32x2 %0, %1, %2, %3;" : "=l"(d) : "l"(a), "l"(b), "l"(c)); return d;
}
__device__ __forceinline__ ull add2(ull a, ull b){
    ull d; asm("add.rn.f32x2 %0, %1, %2;" : "=l"(d) : "l"(a), "l"(b)); return d;
}

// ---- tf32 helpers ----
__device__ __forceinline__ uint32_t totf(float f){
    uint32_t u; asm("cvt.rna.tf32.f32 %0, %1;" : "=r"(u) : "f"(f)); return u;
}
__device__ __forceinline__ void mma_tf32(float d[4], const uint32_t a[4], const uint32_t b[2]){
    asm("mma.sync.aligned.m16n8k8.row.col.f32.tf32.tf32.f32 "
        "{%0,%1,%2,%3},{%4,%5,%6,%7},{%8,%9},{%0,%1,%2,%3};"
        : "+f"(d[0]), "+f"(d[1]), "+f"(d[2]), "+f"(d[3])
        : "r"(a[0]), "r"(a[1]), "r"(a[2]), "r"(a[3]), "r"(b[0]), "r"(b[1]));
}

__device__ __forceinline__ float gelu_tanh(float x){
    float x3 = x*x*x;
    float t = tanhf(0.7978845608028654f*(x + 0.044715f*x3));
    return 0.5f*x*(1.0f + t);
}

// ---- layernorm: 8 threads/row; row-major src/dst; dead rows zero-filled ----
__device__ __forceinline__ void layernorm_rm(const float* __restrict__ src,
        float* __restrict__ dst, const float* __restrict__ g,
        const float* __restrict__ b, int valid)
{
    const int t   = threadIdx.x;
    const int row = t >> 3;           // 64 rows
    const int e   = t & 7;
    float* dr = dst + row*SX;
    if (row < valid){
        const unsigned gmask = 0xFFu << ((t & 31) & ~7);
        const float* xr = src + row*SX;
        float s = 0.f, s2 = 0.f;
        #pragma unroll
        for (int i = 0; i < 16; i++){
            float v = xr[e + 8*i];
            s += v; s2 = fmaf(v, v, s2);
        }
        s  += __shfl_xor_sync(gmask, s, 1);  s2 += __shfl_xor_sync(gmask, s2, 1);
        s  += __shfl_xor_sync(gmask, s, 2);  s2 += __shfl_xor_sync(gmask, s2, 2);
        s  += __shfl_xor_sync(gmask, s, 4);  s2 += __shfl_xor_sync(gmask, s2, 4);
        const float m    = s * 0.0078125f;
        const float rstd = rsqrtf(s2*0.0078125f - m*m + 1e-5f);
        #pragma unroll
        for (int i = 0; i < 16; i++){
            int c = e + 8*i;
            dr[c] = (xr[c] - m)*rstd*g[c] + b[c];
        }
    } else {
        #pragma unroll
        for (int i = 0; i < 16; i++) dr[e + 8*i] = 0.f;   // keep MMA inputs clean
    }
}

// ---- tensor-core GEMM warp tile: 16 rows x 32 cols via m16n8k8 tf32 ----
// src row-major (stride SS, smem), W row-major [IC][OC] (global), dst smem (stride DS).
// MODE 0 = store, 1 = add into dst, 2 = gelu then store.
template<int IC, int OC, int SS, int DS, int MODE>
__device__ __forceinline__ void mma_tile(const float* __restrict__ src,
        const float* __restrict__ W, const float* __restrict__ bias,
        float* __restrict__ dst, int m0, int n0)
{
    const int lane = threadIdx.x & 31;
    const int g    = lane >> 2;
    const int tig  = lane & 3;
    const int NK   = IC / 8;

    float d[4][4];
    #pragma unroll
    for (int nt = 0; nt < 4; nt++){
        const float2 bb = *(const float2*)(bias + n0 + nt*8 + 2*tig);
        d[nt][0] = bb.x; d[nt][1] = bb.y; d[nt][2] = bb.x; d[nt][3] = bb.y;
    }

    const float* s0 = src + (m0 + g)*SS + tig;
    const float* s1 = src + (m0 + g + 8)*SS + tig;
    const float* Wb = W + n0 + g;

    // raw-float double buffers (cvt deferred to just before mma)
    float aC[4], bC[4][2];
    aC[0] = s0[0]; aC[1] = s1[0]; aC[2] = s0[4]; aC[3] = s1[4];
    #pragma unroll
    for (int nt = 0; nt < 4; nt++){
        bC[nt][0] = __ldg(Wb + tig*OC + nt*8);
        bC[nt][1] = __ldg(Wb + (tig+4)*OC + nt*8);
    }

    #pragma unroll 1
    for (int ks = 0; ks < NK; ks++){
        const int k1 = (ks + 1 < NK) ? (ks + 1)*8 : ks*8;
        float aN[4], bN[4][2];
        aN[0] = s0[k1]; aN[1] = s1[k1]; aN[2] = s0[k1+4]; aN[3] = s1[k1+4];
        const float* Wk = Wb + k1*OC;
        #pragma unroll
        for (int nt = 0; nt < 4; nt++){
            bN[nt][0] = __ldg(Wk + tig*OC + nt*8);
            bN[nt][1] = __ldg(Wk + (tig+4)*OC + nt*8);
        }
        uint32_t ua[4];
        #pragma unroll
        for (int i = 0; i < 4; i++) ua[i] = totf(aC[i]);
        #pragma unroll
        for (int nt = 0; nt < 4; nt++){
            uint32_t ub[2] = { totf(bC[nt][0]), totf(bC[nt][1]) };
            mma_tf32(d[nt], ua, ub);
        }
        #pragma unroll
        for (int i = 0; i < 4; i++) aC[i] = aN[i];
        #pragma unroll
        for (int nt = 0; nt < 4; nt++){ bC[nt][0] = bN[nt][0]; bC[nt][1] = bN[nt][1]; }
    }

    #pragma unroll
    for (int nt = 0; nt < 4; nt++){
        const int c  = n0 + nt*8 + 2*tig;
        float* p0 = dst + (m0 + g)*DS + c;
        float* p1 = dst + (m0 + g + 8)*DS + c;
        if (MODE == 0){
            *(float2*)p0 = make_float2(d[nt][0], d[nt][1]);
            *(float2*)p1 = make_float2(d[nt][2], d[nt][3]);
        } else if (MODE == 1){
            float2 x0 = *(float2*)p0, x1 = *(float2*)p1;
            x0.x += d[nt][0]; x0.y += d[nt][1]; *(float2*)p0 = x0;
            x1.x += d[nt][2]; x1.y += d[nt][3]; *(float2*)p1 = x1;
        } else {
            *(float2*)p0 = make_float2(gelu_tanh(d[nt][0]), gelu_tanh(d[nt][1]));
            *(float2*)p1 = make_float2(gelu_tanh(d[nt][2]), gelu_tanh(d[nt][3]));
        }
    }
}

// ---- attention: 2 threads per (head,row); PAIR-SCOPED shuffles; row-major I/O ----
__device__ __forceinline__ void attention_rm(const float* __restrict__ Qb,
        const float* __restrict__ Kb, const float* __restrict__ Vb,
        float* __restrict__ Ho, int valid)
{
    const int t    = threadIdx.x;
    const int lane = t & 31;
    const int half = t & 1;
    const int u    = t >> 1;          // 256 units
    const int head = u >> 6;
    const int row  = u & 63;
    const int base = head * DHn;
    const float scale = 0.17677669529663687f; // 1/sqrt(32)
    const unsigned pmask = 0x3u << (lane & 30);

    if (row < valid){
        ull qp[16];
        const ull* qpt = (const ull*)(Qb + row*SX + base);
        #pragma unroll
        for (int j = 0; j < 16; j++) qp[j] = qpt[j];

        const int tt0 = half << 5;
        float s[32];
        float m = -1e30f;
        #pragma unroll
        for (int i = 0; i < 32; ++i){
            const int tt = tt0 + i;
            if (tt < valid){
                const ull* kpt = (const ull*)(Kb + tt*SX + base);
                ull acc2 = pk2(0.f, 0.f);
                #pragma unroll
                for (int j = 0; j < 16; j++) acc2 = fma2(qp[j], kpt[j], acc2);
                float lo, hi; upk2(acc2, lo, hi);
                s[i] = (lo + hi) * scale;
                m = fmaxf(m, s[i]);
            } else s[i] = -1e30f;
        }
        m = fmaxf(m, __shfl_xor_sync(pmask, m, 1));
        float sum = 0.f;
        #pragma unroll
        for (int i = 0; i < 32; ++i){
            const int tt = tt0 + i;
            float e = (tt < valid) ? __expf(s[i] - m) : 0.f;
            s[i] = e; sum += e;
        }
        sum += __shfl_xor_sync(pmask, sum, 1);

        ull op[16];
        #pragma unroll
        for (int j = 0; j < 16; j++) op[j] = pk2(0.f, 0.f);
        #pragma unroll
        for (int i = 0; i < 32; ++i){
            const int tt = tt0 + i;
            if (tt < valid){
                const ull ad = pk2(s[i], s[i]);
                const ull* vpt = (const ull*)(Vb + tt*SX + base);
                #pragma unroll
                for (int j = 0; j < 16; j++) op[j] = fma2(ad, vpt[j], op[j]);
            }
        }
        const float inv = 1.0f / sum;
        #pragma unroll
        for (int j = 0; j < 16; j++)
            op[j] = add2(op[j], __shfl_xor_sync(pmask, op[j], 1));
        const int j0 = half << 3;
        #pragma unroll
        for (int jj = 0; jj < 8; jj++){
            const int j = j0 + jj;
            float lo, hi; upk2(op[j], lo, hi);
            *(float2*)(Ho + row*SX + base + 2*j) = make_float2(lo*inv, hi*inv);
        }
    }
}

#define SMEM_FLOATS (5*Sn*SX + 2*Sn*16)
#define SMEM_BYTES  (SMEM_FLOATS*4)

__global__ void __launch_bounds__(NTHREADS, 1) rowinteraction_kernel(
    const float* __restrict__ emb,  const float* __restrict__ cls,
    const float* __restrict__ ln1g, const float* __restrict__ ln1b,
    const float* __restrict__ wq,   const float* __restrict__ bq,
    const float* __restrict__ wk,   const float* __restrict__ bk,
    const float* __restrict__ wv,   const float* __restrict__ bv,
    const float* __restrict__ wo,   const float* __restrict__ bo,
    const float* __restrict__ ln2g, const float* __restrict__ ln2b,
    const float* __restrict__ w1,   const float* __restrict__ b1,
    const float* __restrict__ w2,   const float* __restrict__ b2,
    const float* __restrict__ og,   const float* __restrict__ ob,
    const int*   __restrict__ dvec, float* __restrict__ out)
{
    extern __shared__ float smf[];
    float* X  = smf;                 // [64][132] residual
    float* H  = X  + Sn*SX;          // [64][132] ln out / attn out
    float* Qb = H  + Sn*SX;          // [64][132]
    float* Kb = Qb + Sn*SX;
    float* Vb = Kb + Sn*SX;
    float* FF = Qb;                  // [64][260] overlays Q+K (16640 <= 16896)
    float* RC = Vb + Sn*SX;          // rope cos [64][16]
    float* RS = RC + Sn*16;

    const int tid   = threadIdx.x;
    const int warp  = tid >> 5;
    const int n     = blockIdx.x;
    const int bidx  = n >> 10;        // T = 1024
    const int valid = dvec[bidx] + Cn;          // 4..63

    for (int idx = tid; idx < Sn*16; idx += NTHREADS){
        int pos = idx >> 4, f = idx & 15;
        float inv = expf(-((float)(2*f) / (float)DHn) * logf(100000.0f));
        float ang = (float)pos * inv;
        RC[idx] = cosf(ang); RS[idx] = sinf(ang);
    }
    for (int idx = tid; idx < Sn*En; idx += NTHREADS){
        int r = idx >> 7, c = idx & 127;
        float v = (r < Cn) ? cls[r*En + c] : emb[((size_t)n*Sn + r)*En + c];
        X[r*SX + c] = v;
    }
    __syncthreads();

    const int mtw = warp >> 2;        // this warp's base m-tile
    const int ncw = warp & 3;         // this warp's n-chunk

    for (int l = 0; l < Ln; ++l){
        layernorm_rm(X, H, ln1g + l*En, ln1b + l*En, valid);
        __syncthreads();
        // fused QKV: 3 rotated tasks per warp (48 tasks total, full coverage)
        {
            const float* Ws[3] = { wq + l*En*En, wk + l*En*En, wv + l*En*En };
            const float* bs[3] = { bq + l*En,    bk + l*En,    bv + l*En    };
            float* ds[3]       = { Qb, Kb, Vb };
            #pragma unroll
            for (int i = 0; i < 3; i++){
                const int mt = (mtw + i) & 3;
                if (mt*16 < valid)
                    mma_tile<En, En, SX, SX, 0>(H, Ws[i], bs[i], ds[i], mt*16, ncw*32);
            }
        }
        __syncthreads();
        // RoPE in place on live rows (row-major Q/K)
        for (int idx = tid; idx < Sn*NHn*16; idx += NTHREADS){
            int row = idx >> 6;
            if (row < valid){
                int hj = idx & 63; int h = hj >> 4; int j = hj & 15;
                float cc = RC[row*16 + j], ss = RS[row*16 + j];
                int o1 = row*SX + h*DHn + j, o2 = o1 + 16;
                float q1 = Qb[o1], q2 = Qb[o2];
                Qb[o1] = q1*cc - q2*ss;  Qb[o2] = q2*cc + q1*ss;
                float k1 = Kb[o1], k2 = Kb[o2];
                Kb[o1] = k1*cc - k2*ss;  Kb[o2] = k2*cc + k1*ss;
            }
        }
        __syncthreads();
        attention_rm(Qb, Kb, Vb, H, valid);
        __syncthreads();
        if (mtw*16 < valid)           // x += o @ wo + bo
            mma_tile<En, En, SX, SX, 1>(H, wo + l*En*En, bo + l*En, X, mtw*16, ncw*32);
        __syncthreads();
        layernorm_rm(X, H, ln2g + l*En, ln2b + l*En, valid);
        __syncthreads();
        // w1: gelu(h2 @ w1 + b1) -> FF ; 2 rotated tasks per warp (32 tasks)
        #pragma unroll
        for (int i = 0; i < 2; i++){
            const int mt = (mtw + 2*i) & 3;
            if (mt*16 < valid)
                mma_tile<En, FFn, SX, SF, 2>(H, w1 + l*En*FFn, b1 + l*FFn, FF,
                                             mt*16, (ncw + 4*i)*32);
        }
        __syncthreads();
        if (mtw*16 < valid)           // x += ff @ w2 + b2
            mma_tile<FFn, En, SF, SX, 1>(FF, w2 + l*FFn*En, b2 + l*En, X, mtw*16, ncw*32);
        __syncthreads();
    }

    // Epilogue: out-layernorm rows 0..3, write (B,T,C*E)
    const int lane = tid & 31;
    if (warp < Cn){
        const float4 xv = *(const float4*)(X + warp*SX + lane*4);
        float s  = xv.x + xv.y + xv.z + xv.w;
        float s2 = xv.x*xv.x + xv.y*xv.y + xv.z*xv.z + xv.w*xv.w;
        #pragma unroll
        for (int o = 16; o; o >>= 1){
            s  += __shfl_xor_sync(0xffffffffu, s,  o);
            s2 += __shfl_xor_sync(0xffffffffu, s2, o);
        }
        const float m    = s * 0.0078125f;
        const float rstd = rsqrtf(s2*0.0078125f - m*m + 1e-5f);
        const float4 gv  = *(const float4*)(og + lane*4);
        const float4 bv4 = *(const float4*)(ob + lane*4);
        float4 ovv;
        ovv.x = (xv.x - m)*rstd*gv.x + bv4.x;
        ovv.y = (xv.y - m)*rstd*gv.y + bv4.y;
        ovv.z = (xv.z - m)*rstd*gv.z + bv4.z;
        ovv.w = (xv.w - m)*rstd*gv.w + bv4.w;
        *(float4*)(out + (size_t)n*(Cn*En) + warp*En + lane*4) = ovv;
    }
}

extern "C" void kernel_launch(void* const* d_in, const int* in_sizes, int n_in,
                              void* d_out, int out_size)
{
    (void)in_sizes; (void)n_in; (void)out_size;
    cudaFuncSetAttribute(rowinteraction_kernel,
                         cudaFuncAttributeMaxDynamicSharedMemorySize, SMEM_BYTES);
    rowinteraction_kernel<<<Bn*Tn, NTHREADS, SMEM_BYTES>>>(
        (const float*)d_in[0],  (const float*)d_in[1],
        (const float*)d_in[2],  (const float*)d_in[3],
        (const float*)d_in[4],  (const float*)d_in[5],
        (const float*)d_in[6],  (const float*)d_in[7],
        (const float*)d_in[8],  (const float*)d_in[9],
        (const float*)d_in[10], (const float*)d_in[11],
        (const float*)d_in[12], (const float*)d_in[13],
        (const float*)d_in[14], (const float*)d_in[15],
        (const float*)d_in[16], (const float*)d_in[17],
        (const float*)d_in[18], (const float*)d_in[19],
        (const int*)d_in[20],   (float*)d_out);
}

// round 10
// speedup vs baseline: 2.1863x; 1.3113x over previous
#include <cuda_runtime.h>
#include <math.h>
#include <stdint.h>

#define Bn 4
#define Tn 1024
#define Sn 64
#define En 128
#define NHn 4
#define DHn 32
#define FFn 256
#define Ln 3
#define Cn 4
#define SX 132            // row-major stride; 132 mod 32 = 4 -> conflict-free frags
#define SF 260            // FF stride; 260 mod 32 = 4
#define SP 68             // score-matrix stride; 68 mod 32 = 4
#define NTHREADS 512

// ---- tf32 helpers ----
__device__ __forceinline__ uint32_t totf(float f){
    uint32_t u; asm("cvt.rna.tf32.f32 %0, %1;" : "=r"(u) : "f"(f)); return u;
}
__device__ __forceinline__ void mma_tf32(float d[4], const uint32_t a[4], const uint32_t b[2]){
    asm("mma.sync.aligned.m16n8k8.row.col.f32.tf32.tf32.f32 "
        "{%0,%1,%2,%3},{%4,%5,%6,%7},{%8,%9},{%0,%1,%2,%3};"
        : "+f"(d[0]), "+f"(d[1]), "+f"(d[2]), "+f"(d[3])
        : "r"(a[0]), "r"(a[1]), "r"(a[2]), "r"(a[3]), "r"(b[0]), "r"(b[1]));
}

__device__ __forceinline__ float gelu_tanh(float x){
    float x3 = x*x*x;
    float t = tanhf(0.7978845608028654f*(x + 0.044715f*x3));
    return 0.5f*x*(1.0f + t);
}

// ---- layernorm: 8 threads/row; row-major; dead rows zero-filled ----
__device__ __forceinline__ void layernorm_rm(const float* __restrict__ src,
        float* __restrict__ dst, const float* __restrict__ g,
        const float* __restrict__ b, int valid)
{
    const int t   = threadIdx.x;
    const int row = t >> 3;
    const int e   = t & 7;
    float* dr = dst + row*SX;
    if (row < valid){
        const unsigned gmask = 0xFFu << ((t & 31) & ~7);
        const float* xr = src + row*SX;
        float s = 0.f, s2 = 0.f;
        #pragma unroll
        for (int i = 0; i < 16; i++){
            float v = xr[e + 8*i];
            s += v; s2 = fmaf(v, v, s2);
        }
        s  += __shfl_xor_sync(gmask, s, 1);  s2 += __shfl_xor_sync(gmask, s2, 1);
        s  += __shfl_xor_sync(gmask, s, 2);  s2 += __shfl_xor_sync(gmask, s2, 2);
        s  += __shfl_xor_sync(gmask, s, 4);  s2 += __shfl_xor_sync(gmask, s2, 4);
        const float m    = s * 0.0078125f;
        const float rstd = rsqrtf(s2*0.0078125f - m*m + 1e-5f);
        #pragma unroll
        for (int i = 0; i < 16; i++){
            int c = e + 8*i;
            dr[c] = (xr[c] - m)*rstd*g[c] + b[c];
        }
    } else {
        #pragma unroll
        for (int i = 0; i < 16; i++) dr[e + 8*i] = 0.f;
    }
}

// ---- dense tensor-core GEMM warp tile: 16 rows x 32 cols (weights from global) ----
template<int IC, int OC, int SS, int DS, int MODE>
__device__ __forceinline__ void mma_tile(const float* __restrict__ src,
        const float* __restrict__ W, const float* __restrict__ bias,
        float* __restrict__ dst, int m0, int n0)
{
    const int lane = threadIdx.x & 31;
    const int g    = lane >> 2;
    const int tig  = lane & 3;
    const int NK   = IC / 8;

    float d[4][4];
    #pragma unroll
    for (int nt = 0; nt < 4; nt++){
        const float2 bb = *(const float2*)(bias + n0 + nt*8 + 2*tig);
        d[nt][0] = bb.x; d[nt][1] = bb.y; d[nt][2] = bb.x; d[nt][3] = bb.y;
    }

    const float* s0 = src + (m0 + g)*SS + tig;
    const float* s1 = src + (m0 + g + 8)*SS + tig;
    const float* Wb = W + n0 + g;

    float aC[4], bC[4][2];
    aC[0] = s0[0]; aC[1] = s1[0]; aC[2] = s0[4]; aC[3] = s1[4];
    #pragma unroll
    for (int nt = 0; nt < 4; nt++){
        bC[nt][0] = __ldg(Wb + tig*OC + nt*8);
        bC[nt][1] = __ldg(Wb + (tig+4)*OC + nt*8);
    }

    #pragma unroll 1
    for (int ks = 0; ks < NK; ks++){
        const int k1 = (ks + 1 < NK) ? (ks + 1)*8 : ks*8;
        float aN[4], bN[4][2];
        aN[0] = s0[k1]; aN[1] = s1[k1]; aN[2] = s0[k1+4]; aN[3] = s1[k1+4];
        const float* Wk = Wb + k1*OC;
        #pragma unroll
        for (int nt = 0; nt < 4; nt++){
            bN[nt][0] = __ldg(Wk + tig*OC + nt*8);
            bN[nt][1] = __ldg(Wk + (tig+4)*OC + nt*8);
        }
        uint32_t ua[4];
        #pragma unroll
        for (int i = 0; i < 4; i++) ua[i] = totf(aC[i]);
        #pragma unroll
        for (int nt = 0; nt < 4; nt++){
            uint32_t ub[2] = { totf(bC[nt][0]), totf(bC[nt][1]) };
            mma_tf32(d[nt], ua, ub);
        }
        #pragma unroll
        for (int i = 0; i < 4; i++) aC[i] = aN[i];
        #pragma unroll
        for (int nt = 0; nt < 4; nt++){ bC[nt][0] = bN[nt][0]; bC[nt][1] = bN[nt][1]; }
    }

    #pragma unroll
    for (int nt = 0; nt < 4; nt++){
        const int c  = n0 + nt*8 + 2*tig;
        float* p0 = dst + (m0 + g)*DS + c;
        float* p1 = dst + (m0 + g + 8)*DS + c;
        if (MODE == 0){
            *(float2*)p0 = make_float2(d[nt][0], d[nt][1]);
            *(float2*)p1 = make_float2(d[nt][2], d[nt][3]);
        } else if (MODE == 1){
            float2 x0 = *(float2*)p0, x1 = *(float2*)p1;
            x0.x += d[nt][0]; x0.y += d[nt][1]; *(float2*)p0 = x0;
            x1.x += d[nt][2]; x1.y += d[nt][3]; *(float2*)p1 = x1;
        } else {
            *(float2*)p0 = make_float2(gelu_tanh(d[nt][0]), gelu_tanh(d[nt][1]));
            *(float2*)p1 = make_float2(gelu_tanh(d[nt][2]), gelu_tanh(d[nt][3]));
        }
    }
}

#define SMEM_FLOATS (5*Sn*SX + 2*Sn*16 + 2*Sn*SP)
#define SMEM_BYTES  (SMEM_FLOATS*4)

__global__ void __launch_bounds__(NTHREADS, 1) rowinteraction_kernel(
    const float* __restrict__ emb,  const float* __restrict__ cls,
    const float* __restrict__ ln1g, const float* __restrict__ ln1b,
    const float* __restrict__ wq,   const float* __restrict__ bq,
    const float* __restrict__ wk,   const float* __restrict__ bk,
    const float* __restrict__ wv,   const float* __restrict__ bv,
    const float* __restrict__ wo,   const float* __restrict__ bo,
    const float* __restrict__ ln2g, const float* __restrict__ ln2b,
    const float* __restrict__ w1,   const float* __restrict__ b1,
    const float* __restrict__ w2,   const float* __restrict__ b2,
    const float* __restrict__ og,   const float* __restrict__ ob,
    const int*   __restrict__ dvec, float* __restrict__ out)
{
    extern __shared__ float smf[];
    float* X  = smf;                 // [64][132] residual
    float* H  = X  + Sn*SX;          // [64][132] ln out / attn out
    float* Qb = H  + Sn*SX;
    float* Kb = Qb + Sn*SX;
    float* Vb = Kb + Sn*SX;
    float* FF = Qb;                  // [64][260] overlays Q+K
    float* RC = Vb + Sn*SX;          // rope cos [64][16]
    float* RS = RC + Sn*16;
    float* SS = RS + Sn*16;          // scores, 2 heads x [64][68]

    const int tid   = threadIdx.x;
    const int warp  = tid >> 5;
    const int lane  = tid & 31;
    const int g     = lane >> 2;
    const int tig   = lane & 3;
    const int n     = blockIdx.x;
    const int bidx  = n >> 10;        // T = 1024
    const int valid = dvec[bidx] + Cn;          // 4..63
    const float scale = 0.17677669529663687f;   // 1/sqrt(32)

    for (int idx = tid; idx < Sn*16; idx += NTHREADS){
        int pos = idx >> 4, f = idx & 15;
        float inv = expf(-((float)(2*f) / (float)DHn) * logf(100000.0f));
        float ang = (float)pos * inv;
        RC[idx] = cosf(ang); RS[idx] = sinf(ang);
    }
    for (int idx = tid; idx < Sn*En; idx += NTHREADS){
        int r = idx >> 7, c = idx & 127;
        float v = (r < Cn) ? cls[r*En + c] : emb[((size_t)n*Sn + r)*En + c];
        X[r*SX + c] = v;
    }
    __syncthreads();

    const int mtw = warp >> 2;        // dense-GEMM m-tile
    const int ncw = warp & 3;         // dense-GEMM n-chunk

    for (int l = 0; l < Ln; ++l){
        layernorm_rm(X, H, ln1g + l*En, ln1b + l*En, valid);
        __syncthreads();
        {   // fused QKV: 3 rotated tasks per warp
            const float* Ws[3] = { wq + l*En*En, wk + l*En*En, wv + l*En*En };
            const float* bs[3] = { bq + l*En,    bk + l*En,    bv + l*En    };
            float* ds[3]       = { Qb, Kb, Vb };
            #pragma unroll
            for (int i = 0; i < 3; i++){
                const int mt = (mtw + i) & 3;
                if (mt*16 < valid)
                    mma_tile<En, En, SX, SX, 0>(H, Ws[i], bs[i], ds[i], mt*16, ncw*32);
            }
        }
        __syncthreads();
        // RoPE on live rows + ZERO dead K/V rows (NaN/garbage barrier for mma)
        for (int idx = tid; idx < Sn*NHn*16; idx += NTHREADS){
            int row = idx >> 6;
            if (row < valid){
                int hj = idx & 63; int h = hj >> 4; int j = hj & 15;
                float cc = RC[row*16 + j], ss = RS[row*16 + j];
                int o1 = row*SX + h*DHn + j, o2 = o1 + 16;
                float q1 = Qb[o1], q2 = Qb[o2];
                Qb[o1] = q1*cc - q2*ss;  Qb[o2] = q2*cc + q1*ss;
                float k1 = Kb[o1], k2 = Kb[o2];
                Kb[o1] = k1*cc - k2*ss;  Kb[o2] = k2*cc + k1*ss;
            } else {
                int c = (idx & 63) << 1;              // 2 cols per slot
                Kb[row*SX + c] = 0.f; Kb[row*SX + c + 1] = 0.f;
                Vb[row*SX + c] = 0.f; Vb[row*SX + c + 1] = 0.f;
            }
        }
        __syncthreads();

        // ---- attention via tensor cores; two head-pair passes ----
        for (int hp = 0; hp < 2; hp++){
            // S = Q K^T (raw, scale applied in softmax)
            {
                const int h2 = warp >> 3, mt = (warp >> 1) & 3, nh = warp & 1;
                const int qbase = (hp*2 + h2)*DHn;
                const int m0 = mt*16;
                if (m0 < valid){
                    float dS[4][4];
                    #pragma unroll
                    for (int nt = 0; nt < 4; nt++)
                        dS[nt][0] = dS[nt][1] = dS[nt][2] = dS[nt][3] = 0.f;
                    const float* q0 = Qb + (m0 + g)*SX + qbase;
                    const float* q1 = q0 + 8*SX;
                    #pragma unroll
                    for (int ks = 0; ks < 4; ks++){
                        const int k0 = ks*8;
                        uint32_t ua[4] = { totf(q0[k0+tig]), totf(q1[k0+tig]),
                                           totf(q0[k0+tig+4]), totf(q1[k0+tig+4]) };
                        #pragma unroll
                        for (int nt = 0; nt < 4; nt++){
                            const int n0 = nh*32 + nt*8;
                            if (n0 < valid){
                                const float* kp = Kb + (n0 + g)*SX + qbase + k0;
                                uint32_t ub[2] = { totf(kp[tig]), totf(kp[tig+4]) };
                                mma_tf32(dS[nt], ua, ub);
                            }
                        }
                    }
                    float* Sp = SS + h2*(Sn*SP);
                    #pragma unroll
                    for (int nt = 0; nt < 4; nt++){
                        const int n0 = nh*32 + nt*8;
                        if (n0 < valid){
                            float* p = Sp + (m0 + g)*SP + n0 + 2*tig;
                            *(float2*)p          = make_float2(dS[nt][0], dS[nt][1]);
                            *(float2*)(p + 8*SP) = make_float2(dS[nt][2], dS[nt][3]);
                        }
                    }
                }
            }
            __syncthreads();
            // softmax: 4 threads/row over 128 rows; writes normalized P, zeros masked cols
            {
                const int r   = tid >> 2;          // 0..127
                const int q4  = tid & 3;
                const int h2  = r >> 6, row = r & 63;
                if (row < valid){
                    const unsigned gmask = 0xFu << (lane & 28);
                    float* Sr = SS + h2*(Sn*SP) + row*SP;
                    float sv[16];
                    float m = -1e30f;
                    #pragma unroll
                    for (int i = 0; i < 16; i++){
                        int c = q4 + 4*i;
                        if (c < valid){ sv[i] = Sr[c]*scale; m = fmaxf(m, sv[i]); }
                        else sv[i] = 0.f;
                    }
                    m = fmaxf(m, __shfl_xor_sync(gmask, m, 1));
                    m = fmaxf(m, __shfl_xor_sync(gmask, m, 2));
                    float sum = 0.f;
                    #pragma unroll
                    for (int i = 0; i < 16; i++){
                        int c = q4 + 4*i;
                        float e = (c < valid) ? __expf(sv[i] - m) : 0.f;
                        sv[i] = e; sum += e;
                    }
                    sum += __shfl_xor_sync(gmask, sum, 1);
                    sum += __shfl_xor_sync(gmask, sum, 2);
                    const float inv = 1.0f / sum;
                    #pragma unroll
                    for (int i = 0; i < 16; i++) Sr[q4 + 4*i] = sv[i]*inv;
                }
            }
            __syncthreads();
            // O = P V  -> H
            {
                const int h2 = warp >> 3, mt = (warp >> 1) & 3, nh = warp & 1;
                const int obase = (hp*2 + h2)*DHn + nh*16;
                const int m0 = mt*16;
                if (m0 < valid){
                    float dO[2][4];
                    #pragma unroll
                    for (int nt = 0; nt < 2; nt++)
                        dO[nt][0] = dO[nt][1] = dO[nt][2] = dO[nt][3] = 0.f;
                    const float* Pp = SS + h2*(Sn*SP);
                    const float* p0 = Pp + (m0 + g)*SP;
                    const float* p1 = p0 + 8*SP;
                    const int NKS = (valid + 7) >> 3;
                    #pragma unroll 1
                    for (int ks = 0; ks < NKS; ks++){
                        const int k0 = ks*8;
                        uint32_t ua[4] = { totf(p0[k0+tig]), totf(p1[k0+tig]),
                                           totf(p0[k0+tig+4]), totf(p1[k0+tig+4]) };
                        #pragma unroll
                        for (int nt = 0; nt < 2; nt++){
                            const float* vp = Vb + (k0 + tig)*SX + obase + nt*8 + g;
                            uint32_t ub[2] = { totf(vp[0]), totf(vp[4*SX]) };
                            mma_tf32(dO[nt], ua, ub);
                        }
                    }
                    #pragma unroll
                    for (int nt = 0; nt < 2; nt++){
                        const int c = obase + nt*8 + 2*tig;
                        float* p = H + (m0 + g)*SX + c;
                        *(float2*)p          = make_float2(dO[nt][0], dO[nt][1]);
                        *(float2*)(p + 8*SX) = make_float2(dO[nt][2], dO[nt][3]);
                    }
                }
            }
            __syncthreads();
        }

        if (mtw*16 < valid)           // x += o @ wo + bo
            mma_tile<En, En, SX, SX, 1>(H, wo + l*En*En, bo + l*En, X, mtw*16, ncw*32);
        __syncthreads();
        layernorm_rm(X, H, ln2g + l*En, ln2b + l*En, valid);
        __syncthreads();
        #pragma unroll
        for (int i = 0; i < 2; i++){  // gelu(h2 @ w1 + b1) -> FF
            const int mt = (mtw + 2*i) & 3;
            if (mt*16 < valid)
                mma_tile<En, FFn, SX, SF, 2>(H, w1 + l*En*FFn, b1 + l*FFn, FF,
                                             mt*16, (ncw + 4*i)*32);
        }
        __syncthreads();
        if (mtw*16 < valid)           // x += ff @ w2 + b2
            mma_tile<FFn, En, SF, SX, 1>(FF, w2 + l*FFn*En, b2 + l*En, X, mtw*16, ncw*32);
        __syncthreads();
    }

    // Epilogue: out-layernorm rows 0..3, write (B,T,C*E)
    if (warp < Cn){
        const float4 xv = *(const float4*)(X + warp*SX + lane*4);
        float s  = xv.x + xv.y + xv.z + xv.w;
        float s2 = xv.x*xv.x + xv.y*xv.y + xv.z*xv.z + xv.w*xv.w;
        #pragma unroll
        for (int o = 16; o; o >>= 1){
            s  += __shfl_xor_sync(0xffffffffu, s,  o);
            s2 += __shfl_xor_sync(0xffffffffu, s2, o);
        }
        const float m    = s * 0.0078125f;
        const float rstd = rsqrtf(s2*0.0078125f - m*m + 1e-5f);
        const float4 gv  = *(const float4*)(og + lane*4);
        const float4 bv4 = *(const float4*)(ob + lane*4);
        float4 ovv;
        ovv.x = (xv.x - m)*rstd*gv.x + bv4.x;
        ovv.y = (xv.y - m)*rstd*gv.y + bv4.y;
        ovv.z = (xv.z - m)*rstd*gv.z + bv4.z;
        ovv.w = (xv.w - m)*rstd*gv.w + bv4.w;
        *(float4*)(out + (size_t)n*(Cn*En) + warp*En + lane*4) = ovv;
    }
}

extern "C" void kernel_launch(void* const* d_in, const int* in_sizes, int n_in,
                              void* d_out, int out_size)
{
    (void)in_sizes; (void)n_in; (void)out_size;
    cudaFuncSetAttribute(rowinteraction_kernel,
                         cudaFuncAttributeMaxDynamicSharedMemorySize, SMEM_BYTES);
    rowinteraction_kernel<<<Bn*Tn, NTHREADS, SMEM_BYTES>>>(
        (const float*)d_in[0],  (const float*)d_in[1],
        (const float*)d_in[2],  (const float*)d_in[3],
        (const float*)d_in[4],  (const float*)d_in[5],
        (const float*)d_in[6],  (const float*)d_in[7],
        (const float*)d_in[8],  (const float*)d_in[9],
        (const float*)d_in[10], (const float*)d_in[11],
        (const float*)d_in[12], (const float*)d_in[13],
        (const float*)d_in[14], (const float*)d_in[15],
        (const float*)d_in[16], (const float*)d_in[17],
        (const float*)d_in[18], (const float*)d_in[19],
        (const int*)d_in[20],   (float*)d_out);
}